// round 3
// baseline (speedup 1.0000x reference)
#include <cuda_runtime.h>

// DWT2 (2x2 Haar) : x[16,64,256,256] f32 -> out[16,256,128,128] f32
//   out[n, i*64+c, y, x] = 0.5 * (s0*a + s1*b + s2*cc + s3*d)
// with a=x[n,c,2y,2x], b=x[n,c,2y,2x+1], cc=x[n,c,2y+1,2x], d=x[n,c,2y+1,2x+1]
// HAAR rows: i0:(+ + + +), i1:(+ + - -), i2:(+ - + -), i3:(+ - - +)

static constexpr int N  = 16;
static constexpr int C  = 64;
static constexpr int H  = 256;
static constexpr int W  = 256;
static constexpr int H2 = H / 2;   // 128
static constexpr int W2 = W / 2;   // 128

// Each thread: float4 from input row 2y and row 2y+1 (4 input cols -> 2 output px)
// Per-thread work along W: W/4 = 64 float4-groups.
static constexpr int XGROUPS = W / 4;                 // 64
static constexpr long long TOTAL = (long long)N * C * H2 * XGROUPS;  // 8,388,608
static constexpr int PLANE = H2 * W2;                 // 16384 (one out-channel plane)
static constexpr int OUT_I_STRIDE = C * PLANE;        // 1,048,576 (stride between Haar bands)

__global__ __launch_bounds__(256) void dwt2_haar_kernel(
    const float* __restrict__ x, float* __restrict__ out)
{
    long long idx = (long long)blockIdx.x * blockDim.x + threadIdx.x;
    if (idx >= TOTAL) return;

    int xg = (int)(idx % XGROUPS);              // which float4 group along W
    int y  = (int)((idx / XGROUPS) % H2);       // output row
    int c  = (int)((idx / ((long long)XGROUPS * H2)) % C);
    int n  = (int)( idx / ((long long)XGROUPS * H2 * C));

    // input: rows 2y and 2y+1, columns [4*xg, 4*xg+3]
    const float* row0 = x + (((long long)(n * C + c) * H + 2 * y) * W + 4 * xg);
    const float* row1 = row0 + W;

    float4 r0 = *reinterpret_cast<const float4*>(row0);
    float4 r1 = *reinterpret_cast<const float4*>(row1);

    // two output pixels: (a,b / c,d) pairs
    float a0 = r0.x, b0 = r0.y, a1 = r0.z, b1 = r0.w;
    float c0 = r1.x, d0 = r1.y, c1 = r1.z, d1 = r1.w;

    // butterfly (save adds): sum/diff stages
    float ab0p = a0 + b0, ab0m = a0 - b0;
    float cd0p = c0 + d0, cd0m = c0 - d0;
    float ab1p = a1 + b1, ab1m = a1 - b1;
    float cd1p = c1 + d1, cd1m = c1 - d1;

    float2 o0 = make_float2(0.5f * (ab0p + cd0p), 0.5f * (ab1p + cd1p)); // LL
    float2 o1 = make_float2(0.5f * (ab0p - cd0p), 0.5f * (ab1p - cd1p)); // i=1
    float2 o2 = make_float2(0.5f * (ab0m + cd0m), 0.5f * (ab1m + cd1m)); // i=2
    float2 o3 = make_float2(0.5f * (ab0m - cd0m), 0.5f * (ab1m - cd1m)); // i=3

    // out[n, i*C + c, y, 2*xg .. 2*xg+1]
    long long obase = ((long long)n * 4 * C + c) * PLANE + (long long)y * W2 + 2 * xg;
    float* o = out + obase;
    *reinterpret_cast<float2*>(o)                    = o0;
    *reinterpret_cast<float2*>(o + 1 * OUT_I_STRIDE) = o1;
    *reinterpret_cast<float2*>(o + 2 * OUT_I_STRIDE) = o2;
    *reinterpret_cast<float2*>(o + 3 * OUT_I_STRIDE) = o3;
}

extern "C" void kernel_launch(void* const* d_in, const int* in_sizes, int n_in,
                              void* d_out, int out_size)
{
    const float* x = (const float*)d_in[0];
    float* out = (float*)d_out;

    const int threads = 256;
    const long long blocks = (TOTAL + threads - 1) / threads;  // 32768
    dwt2_haar_kernel<<<(unsigned)blocks, threads>>>(x, out);
}